// round 3
// baseline (speedup 1.0000x reference)
#include <cuda_runtime.h>
#include <math.h>

// ScatTransform1D: direct time-domain complex correlation + modulus.
// y[b,k,t] = | sum_j x[t + j - P] * (fr[k,j] + i*fi[k,j]) |
// Filters are centered & zero-padded to L; filter k's true support is
// [P - M_k, P + M_k] with M_k = ceil(6 * 2^(j + q/16)) (+margin), which cuts
// the FMA count ~4000x vs. using the padded length.

#define KFILT 192
#define QSTEP 16
#define NBATCH 2
#define BLOCK 256
#define RPT 8                    // outputs per thread (consecutive)
#define TILE (BLOCK * RPT)       // 2048 outputs per block
#define CHUNK 1024               // filter taps staged per smem pass
#define XS_LEN (TILE + CHUNK + 16)

__global__ __launch_bounds__(BLOCK)
void scat1d_kernel(const float* __restrict__ x,
                   const float* __restrict__ fr,
                   const float* __restrict__ fi,
                   float* __restrict__ out,
                   int T, int L, int P)
{
    __shared__ __align__(16) float  xs[XS_LEN];
    __shared__ __align__(16) float2 fs[CHUNK];

    const int tile = blockIdx.x;
    const int k    = (KFILT - 1) - blockIdx.y;   // longest filters scheduled first
    const int b    = blockIdx.z;
    const int tid  = threadIdx.x;
    const int t0   = tile * TILE;

    // Effective half-support of filter k (superset of true nonzero region).
    const int j = k / QSTEP, q = k % QSTEP;
    const double e = (double)j + (double)q / (double)QSTEP;
    int M = (int)ceil(6.0 * exp2(e)) + 2;        // +2 margin vs numpy rounding
    if (M > P) M = P;
    const int lo = P - M;
    const int hi = P + M;                        // <= L-1 since L = 2P+1

    const float* xb  = x  + (size_t)b * T;
    const float* frk = fr + (size_t)k * L;
    const float* fik = fi + (size_t)k * L;

    float accr[RPT], acci[RPT];
    #pragma unroll
    for (int r = 0; r < RPT; ++r) { accr[r] = 0.0f; acci[r] = 0.0f; }

    for (int d0 = lo; d0 <= hi; d0 += CHUNK) {
        int len = hi - d0 + 1;
        if (len > CHUNK) len = CHUNK;
        const int len4 = (len + 3) & ~3;

        __syncthreads();
        // Stage x slice covering [t0 + d0 - P, t0 + d0 - P + XS_LEN)
        const int gbase = t0 + d0 - P;
        #pragma unroll 4
        for (int i = tid; i < XS_LEN; i += BLOCK) {
            const int g = gbase + i;
            xs[i] = (g >= 0 && g < T) ? __ldg(xb + g) : 0.0f;
        }
        // Stage filter chunk (zero-fill past the valid taps)
        #pragma unroll 4
        for (int c = tid; c < CHUNK; c += BLOCK) {
            float a = 0.0f, bb = 0.0f;
            if (c < len) {
                const int jj = d0 + c;
                a  = __ldg(frk + jj);
                bb = __ldg(fik + jj);
            }
            fs[c] = make_float2(a, bb);
        }
        __syncthreads();

        // Inner loop: sliding 12-float register window, one float4 smem load
        // per 4 taps, 64 FFMA per 4 taps per thread -> FFMA-pipe bound.
        const float* xbase = xs + tid * RPT;
        float xw[12];
        #pragma unroll
        for (int i = 0; i < 8; ++i) xw[i] = xbase[i];

        for (int c = 0; c < len4; c += 4) {
            const float4 nx = *reinterpret_cast<const float4*>(xbase + c + 8);
            xw[8] = nx.x; xw[9] = nx.y; xw[10] = nx.z; xw[11] = nx.w;
            #pragma unroll
            for (int cc = 0; cc < 4; ++cc) {
                const float2 f = fs[c + cc];
                #pragma unroll
                for (int r = 0; r < RPT; ++r) {
                    accr[r] = fmaf(xw[r + cc], f.x, accr[r]);
                    acci[r] = fmaf(xw[r + cc], f.y, acci[r]);
                }
            }
            #pragma unroll
            for (int i = 0; i < 8; ++i) xw[i] = xw[i + 4];
        }
    }

    // Modulus + vectorized store (t0 + tid*8 is 32B-aligned, T % 8 == 0).
    float res[RPT];
    #pragma unroll
    for (int r = 0; r < RPT; ++r)
        res[r] = sqrtf(accr[r] * accr[r] + acci[r] * acci[r]);

    float4* o = reinterpret_cast<float4*>(
        out + ((size_t)b * KFILT + k) * T + t0 + (size_t)tid * RPT);
    o[0] = make_float4(res[0], res[1], res[2], res[3]);
    o[1] = make_float4(res[4], res[5], res[6], res[7]);
}

extern "C" void kernel_launch(void* const* d_in, const int* in_sizes, int n_in,
                              void* d_out, int out_size)
{
    const float* x  = (const float*)d_in[0];
    const float* fr = (const float*)d_in[1];
    const float* fi = (const float*)d_in[2];
    float* out = (float*)d_out;

    const int T = in_sizes[0] / NBATCH;      // 32768
    const int L = in_sizes[1] / KFILT;       // ~47071 (odd)
    const int P = L / 2;

    dim3 grid(T / TILE, KFILT, NBATCH);
    scat1d_kernel<<<grid, BLOCK>>>(x, fr, fi, out, T, L, P);
}

// round 4
// speedup vs baseline: 1.1170x; 1.1170x over previous
#include <cuda_runtime.h>
#include <math.h>

// ScatTransform1D: direct time-domain complex correlation + modulus.
// y[b,k,t] = | sum_d x[t + d - P] * (fr[k,d] + i*fi[k,d]) |
// Filter k's true support is [P-M_k, P+M_k], M_k = ceil(6*2^(j+q/16)).
//
// FFMA2 version: each 64-bit lane-pair packs two outputs 1024 apart.
//   xsI[i]  = (x[g+i], x[g+i+1024])          packed pair operand (no dup MOVs)
//   fsd[c]  = ({fr,fr}, {fi,fi})             broadcast dup filter operand
//   acc     = fma.rn.f32x2(xw, ff, acc)      2 FMAs / instruction
// Thread tid owns pair-indices tid*4..tid*4+3 (lane stride 32B -> the window
// refill LDS.128s are bank-conflict-free; the old tid*8 layout was 8-way).

#define KFILT 192
#define QSTEP 16
#define NBATCH 2
#define BLOCK 256
#define JPT 4                      // packed pairs per thread (=> 8 outputs)
#define HALF 1024                  // distance between packed outputs
#define TILE 2048                  // outputs per block
#define CHUNK 1024                 // filter taps staged per smem pass
#define XS_PAIRS (HALF + CHUNK + 8)

typedef unsigned long long ull;

#define FMA2(d, a, b) asm("fma.rn.f32x2 %0, %1, %2, %0;" : "+l"(d) : "l"(a), "l"(b))

__device__ __forceinline__ ull pack2(float lo, float hi) {
    return (ull)__float_as_uint(lo) | ((ull)__float_as_uint(hi) << 32);
}

__global__ __launch_bounds__(BLOCK)
void scat1d_kernel(const float* __restrict__ x,
                   const float* __restrict__ fr,
                   const float* __restrict__ fi,
                   float* __restrict__ out,
                   int T, int L, int P)
{
    __shared__ __align__(16) ull        xsI[XS_PAIRS];
    __shared__ __align__(16) ulonglong2 fsd[CHUNK];

    const int tile = blockIdx.x;
    const int k    = (KFILT - 1) - blockIdx.y;   // longest filters first
    const int b    = blockIdx.z;
    const int tid  = threadIdx.x;
    const int t0   = tile * TILE;

    // Effective half-support (superset of true nonzero region).
    const int j = k / QSTEP, q = k % QSTEP;
    const double e = (double)j + (double)q / (double)QSTEP;
    int M = (int)ceil(6.0 * exp2(e)) + 2;
    if (M > P) M = P;
    const int lo = P - M;
    const int hi = P + M;

    const float* xb  = x  + (size_t)b * T;
    const float* frk = fr + (size_t)k * L;
    const float* fik = fi + (size_t)k * L;

    ull accR[JPT], accI[JPT];
    #pragma unroll
    for (int r = 0; r < JPT; ++r) { accR[r] = 0ULL; accI[r] = 0ULL; }

    const int base = tid * JPT;   // this thread's pair-index base

    for (int d0 = lo; d0 <= hi; d0 += CHUNK) {
        int len = hi - d0 + 1;
        if (len > CHUNK) len = CHUNK;
        const int len8 = (len + 7) & ~7;         // unroll-2 period

        __syncthreads();
        // Stage interleaved x pairs: xsI[i] = (x[g+i], x[g+i+HALF])
        const int g = t0 + d0 - P;
        #pragma unroll 4
        for (int i = tid; i < XS_PAIRS; i += BLOCK) {
            const int ga = g + i;
            const int gb = ga + HALF;
            const float a  = (ga >= 0 && ga < T) ? __ldg(xb + ga) : 0.0f;
            const float bb = (gb >= 0 && gb < T) ? __ldg(xb + gb) : 0.0f;
            xsI[i] = pack2(a, bb);
        }
        // Stage duplicated filter taps: ({fr,fr},{fi,fi}); zero past len.
        #pragma unroll 4
        for (int c = tid; c < CHUNK; c += BLOCK) {
            float a = 0.0f, bb = 0.0f;
            if (c < len) {
                const int dd = d0 + c;
                a  = __ldg(frk + dd);
                bb = __ldg(fik + dd);
            }
            fsd[c] = make_ulonglong2(pack2(a, a), pack2(bb, bb));
        }
        __syncthreads();

        // Preload 8-pair window.
        ull w[8];
        {
            const ulonglong2 p0 = *reinterpret_cast<const ulonglong2*>(&xsI[base]);
            const ulonglong2 p1 = *reinterpret_cast<const ulonglong2*>(&xsI[base + 2]);
            const ulonglong2 p2 = *reinterpret_cast<const ulonglong2*>(&xsI[base + 4]);
            const ulonglong2 p3 = *reinterpret_cast<const ulonglong2*>(&xsI[base + 6]);
            w[0] = p0.x; w[1] = p0.y; w[2] = p1.x; w[3] = p1.y;
            w[4] = p2.x; w[5] = p2.y; w[6] = p3.x; w[7] = p3.y;
        }

        // Inner loop: 4 taps/step, 32 FFMA2 + 2 LDS.128 (x) + 4 LDS.128 (f bc).
        // unroll 2 -> window shift copies rename away (period 2).
        #pragma unroll 2
        for (int c = 0; c < len8; c += 4) {
            const ulonglong2 n01 = *reinterpret_cast<const ulonglong2*>(&xsI[base + c + 8]);
            const ulonglong2 n23 = *reinterpret_cast<const ulonglong2*>(&xsI[base + c + 10]);
            #pragma unroll
            for (int cc = 0; cc < 4; ++cc) {
                const ulonglong2 f = fsd[c + cc];
                #pragma unroll
                for (int r = 0; r < JPT; ++r) {
                    FMA2(accR[r], w[r + cc], f.x);
                    FMA2(accI[r], w[r + cc], f.y);
                }
            }
            w[0] = w[4]; w[1] = w[5]; w[2] = w[6]; w[3] = w[7];
            w[4] = n01.x; w[5] = n01.y; w[6] = n23.x; w[7] = n23.y;
        }
    }

    // Modulus + stores: lo halves -> t0+base.., hi halves -> +HALF.
    float rlo[JPT], rhi[JPT];
    #pragma unroll
    for (int r = 0; r < JPT; ++r) {
        const float yr0 = __uint_as_float((unsigned)accR[r]);
        const float yr1 = __uint_as_float((unsigned)(accR[r] >> 32));
        const float yi0 = __uint_as_float((unsigned)accI[r]);
        const float yi1 = __uint_as_float((unsigned)(accI[r] >> 32));
        rlo[r] = sqrtf(yr0 * yr0 + yi0 * yi0);
        rhi[r] = sqrtf(yr1 * yr1 + yi1 * yi1);
    }
    float* obase = out + ((size_t)b * KFILT + k) * T + t0 + base;
    *reinterpret_cast<float4*>(obase)        = make_float4(rlo[0], rlo[1], rlo[2], rlo[3]);
    *reinterpret_cast<float4*>(obase + HALF) = make_float4(rhi[0], rhi[1], rhi[2], rhi[3]);
}

extern "C" void kernel_launch(void* const* d_in, const int* in_sizes, int n_in,
                              void* d_out, int out_size)
{
    const float* x  = (const float*)d_in[0];
    const float* fr = (const float*)d_in[1];
    const float* fi = (const float*)d_in[2];
    float* out = (float*)d_out;

    const int T = in_sizes[0] / NBATCH;      // 32768
    const int L = in_sizes[1] / KFILT;       // ~47053 (odd)
    const int P = L / 2;

    dim3 grid(T / TILE, KFILT, NBATCH);
    scat1d_kernel<<<grid, BLOCK>>>(x, fr, fi, out, T, L, P);
}

// round 8
// speedup vs baseline: 1.5691x; 1.4048x over previous
#include <cuda_runtime.h>
#include <math.h>

// ScatTransform1D via implicit GEMM on fallback HMMA (mma.sync.m16n8k16.bf16),
// bf16 hi/lo split for fp32-grade accuracy (keep xh*fh + xl*fh + xh*fl).
//
// Per block: octave j (16 filters -> N=32 cols re/im), 128 consecutive t (M),
// K = taps looped in 64-tap chunks. A is Toeplitz: A[m][k] = window[m+k], so
// per-lane A fragments are LDS.64 from a 192-entry packed (hi,lo) window array
// converted once per chunk. B fragments come pre-split/pre-laid-out from a
// __device__ bank filled by a prep kernel each launch (deterministic).

#define KFILT 192
#define QSTEP 16
#define NBATCH 2
#define NOCT 12
#define MT_M 128
#define KC 64
#define CHUNK_WORDS 2048           // (2 split)(4 kk)(2 rr)(32 lane)(4 c) words
#define MAX_CHUNKS_TOTAL 1600      // sum over octaves of nc_j (=1477 actual)

__device__ __align__(16) unsigned g_bank[MAX_CHUNKS_TOTAL * CHUNK_WORDS]; // 13MB

static __device__ __forceinline__ unsigned bfpair(float lo, float hi) {
    unsigned r;   // lower 16 bits <- lo (tap k), upper <- hi (tap k+1)
    asm("cvt.rn.bf16x2.f32 %0, %1, %2;" : "=r"(r) : "f"(hi), "f"(lo));
    return r;
}

// Octave support params; MUST be identical in prep + main kernels.
static __device__ __forceinline__ int oct_params(int j, int P, int* lo, int* nc) {
    int off = 0;
    for (int jj = 0; jj <= j; jj++) {
        int M = (int)ceil(6.0 * exp2((double)jj + 0.9375)) + 2;  // max-q support
        if (M > P) M = P;
        int c = (2 * M + KC) / KC;      // ceil((2M+1)/64)
        if (jj < j) off += c;
        else { *lo = P - M; *nc = c; }
    }
    return off * CHUNK_WORDS;
}

// ---------------------------------------------------------------- prep kernel
// Fills g_bank with bf16-split filter taps in b-fragment lane order:
// word index = ((((sp*4 + kk)*2 + rr)*32 + lane)*4 + c)
//   n (output col) = c*8 + (lane>>2); q = n>>1; comp = n&1 (re/im)
//   tap k = kk*16 + rr*8 + (lane&3)*2; global tap d = lo_j + ci*64 + k
// Each word = packed bf16 pair (f[d], f[d+1]); sp=0 -> hi, sp=1 -> residual.
__global__ void prep_bank(const float* __restrict__ fr, const float* __restrict__ fi,
                          int L, int P)
{
    const int j = blockIdx.y;
    int lo, nc;
    const int off = oct_params(j, P, &lo, &nc);
    const int ci = blockIdx.x;
    if (ci >= nc) return;
    unsigned* dst = g_bank + off + ci * CHUNK_WORDS;

    for (int wd = threadIdx.x; wd < CHUNK_WORDS; wd += blockDim.x) {
        const int c    = wd & 3;
        const int lane = (wd >> 2) & 31;
        const int rr   = (wd >> 7) & 1;
        const int kk   = (wd >> 8) & 3;
        const int sp   = (wd >> 10) & 1;
        const int n    = c * 8 + (lane >> 2);
        const float* src = ((n & 1) ? fi : fr) + (size_t)(j * QSTEP + (n >> 1)) * L;
        const int d = lo + ci * KC + kk * 16 + rr * 8 + (lane & 3) * 2;
        const float f0 = (d < L)     ? __ldg(src + d)     : 0.0f;
        const float f1 = (d + 1 < L) ? __ldg(src + d + 1) : 0.0f;
        const unsigned ph = bfpair(f0, f1);
        if (sp == 0) {
            dst[wd] = ph;
        } else {
            const float h0 = __uint_as_float(ph << 16);
            const float h1 = __uint_as_float(ph & 0xFFFF0000u);
            dst[wd] = bfpair(f0 - h0, f1 - h1);
        }
    }
}

// ---------------------------------------------------------------- main kernel
static __device__ __forceinline__ void mma_bf16(float c[4],
                                                unsigned a0, unsigned a1,
                                                unsigned a2, unsigned a3,
                                                unsigned b0, unsigned b1)
{
    asm volatile(
        "mma.sync.aligned.m16n8k16.row.col.f32.bf16.bf16.f32 "
        "{%0,%1,%2,%3}, {%4,%5,%6,%7}, {%8,%9}, {%0,%1,%2,%3};"
        : "+f"(c[0]), "+f"(c[1]), "+f"(c[2]), "+f"(c[3])
        : "r"(a0), "r"(a1), "r"(a2), "r"(a3), "r"(b0), "r"(b1));
}

__global__ __launch_bounds__(128)
void scat_mma_kernel(const float* __restrict__ x, float* __restrict__ out,
                     int T, int L, int P)
{
    __shared__ float wbuf[200];
    __shared__ unsigned long long whl[192];   // low 32b: hi-pair, high 32b: lo-pair

    const int tid  = threadIdx.x;
    const int wix  = tid >> 5;
    const int lane = tid & 31;
    const int t0   = blockIdx.x * MT_M;
    const int j    = (NOCT - 1) - blockIdx.y;    // heavy octaves first
    const int b    = blockIdx.z;

    int lo, nc;
    const int off = oct_params(j, P, &lo, &nc);
    const float* xb = x + (size_t)b * T;

    float acc[2][4][4];
    #pragma unroll
    for (int mt = 0; mt < 2; mt++)
        #pragma unroll
        for (int c = 0; c < 4; c++)
            #pragma unroll
            for (int r = 0; r < 4; r++) acc[mt][c][r] = 0.0f;

    // A-fragment base smem index: m + k with m = wix*32 + (lane>>2),
    // k = 2*(lane&3); (+8 row) and (+8 col) coincide for Toeplitz A.
    const int abase = wix * 32 + (lane >> 2) + (lane & 3) * 2;

    for (int ci = 0; ci < nc; ci++) {
        __syncthreads();
        const int g0 = t0 + lo + ci * KC - P;
        for (int i = tid; i < 194; i += 128) {
            const int g = g0 + i;
            wbuf[i] = (g >= 0 && g < T) ? __ldg(xb + g) : 0.0f;
        }
        __syncthreads();
        for (int i = tid; i < 192; i += 128) {
            const float x0 = wbuf[i], x1 = wbuf[i + 1];
            const unsigned ph = bfpair(x0, x1);
            const float h0 = __uint_as_float(ph << 16);
            const float h1 = __uint_as_float(ph & 0xFFFF0000u);
            const unsigned pl = bfpair(x0 - h0, x1 - h1);
            whl[i] = (unsigned long long)ph | ((unsigned long long)pl << 32);
        }
        __syncthreads();

        const uint4* bg4 = (const uint4*)(g_bank + off + ci * CHUNK_WORDS);
        #pragma unroll
        for (int kk = 0; kk < 4; kk++) {
            // B fragments: 4 coalesced LDG.128 (x/y/z/w = n-tiles 0..3).
            const uint4 bh0 = __ldg(bg4 + (kk * 2 + 0) * 32 + lane);
            const uint4 bh1 = __ldg(bg4 + (kk * 2 + 1) * 32 + lane);
            const uint4 bl0 = __ldg(bg4 + 256 + (kk * 2 + 0) * 32 + lane);
            const uint4 bl1 = __ldg(bg4 + 256 + (kk * 2 + 1) * 32 + lane);
            #pragma unroll
            for (int mt = 0; mt < 2; mt++) {
                const int ai = abase + mt * 16 + kk * 16;
                const unsigned long long pa = whl[ai];
                const unsigned long long pb = whl[ai + 8];
                const unsigned long long pc = whl[ai + 16];
                const unsigned ha = (unsigned)pa, la = (unsigned)(pa >> 32);
                const unsigned hb = (unsigned)pb, lb = (unsigned)(pb >> 32);
                const unsigned hc = (unsigned)pc, lc = (unsigned)(pc >> 32);
                // xh*fh
                mma_bf16(acc[mt][0], ha, hb, hb, hc, bh0.x, bh1.x);
                mma_bf16(acc[mt][1], ha, hb, hb, hc, bh0.y, bh1.y);
                mma_bf16(acc[mt][2], ha, hb, hb, hc, bh0.z, bh1.z);
                mma_bf16(acc[mt][3], ha, hb, hb, hc, bh0.w, bh1.w);
                // xl*fh
                mma_bf16(acc[mt][0], la, lb, lb, lc, bh0.x, bh1.x);
                mma_bf16(acc[mt][1], la, lb, lb, lc, bh0.y, bh1.y);
                mma_bf16(acc[mt][2], la, lb, lb, lc, bh0.z, bh1.z);
                mma_bf16(acc[mt][3], la, lb, lb, lc, bh0.w, bh1.w);
                // xh*fl
                mma_bf16(acc[mt][0], ha, hb, hb, hc, bl0.x, bl1.x);
                mma_bf16(acc[mt][1], ha, hb, hb, hc, bl0.y, bl1.y);
                mma_bf16(acc[mt][2], ha, hb, hb, hc, bl0.z, bl1.z);
                mma_bf16(acc[mt][3], ha, hb, hb, hc, bl0.w, bl1.w);
            }
        }
    }

    // Epilogue: acc cols (2(lane&3), +1) = (re, im) of filter q = c*4 + (lane&3);
    // rows m0 + mt*16 (+8 for regs 2,3).
    const int m0 = t0 + wix * 32 + (lane >> 2);
    #pragma unroll
    for (int mt = 0; mt < 2; mt++)
        #pragma unroll
        for (int c = 0; c < 4; c++) {
            const int q = c * 4 + (lane & 3);
            float* op = out + ((size_t)b * KFILT + j * QSTEP + q) * T + m0 + mt * 16;
            op[0] = sqrtf(acc[mt][c][0] * acc[mt][c][0] + acc[mt][c][1] * acc[mt][c][1]);
            op[8] = sqrtf(acc[mt][c][2] * acc[mt][c][2] + acc[mt][c][3] * acc[mt][c][3]);
        }
}

extern "C" void kernel_launch(void* const* d_in, const int* in_sizes, int n_in,
                              void* d_out, int out_size)
{
    const float* x  = (const float*)d_in[0];
    const float* fr = (const float*)d_in[1];
    const float* fi = (const float*)d_in[2];
    float* out = (float*)d_out;

    const int T = in_sizes[0] / NBATCH;      // 32768
    const int L = in_sizes[1] / KFILT;       // ~47071 (odd)
    const int P = L / 2;

    prep_bank<<<dim3(768, NOCT), 256>>>(fr, fi, L, P);
    scat_mma_kernel<<<dim3(T / MT_M, NOCT, NBATCH), 128>>>(x, out, T, L, P);
}